// round 15
// baseline (speedup 1.0000x reference)
#include <cuda_runtime.h>
#include <cstdint>

#define B_ 8
#define V_ 64
#define E_ 512
#define L_ 4
#define H_ 8
#define D_ 64
#define M_ 1024
#define R_ 128
#define HD_ 512
#define ROWS_ 512
#define LHD_ 2048

// ---------------- scratch ----------------
__device__ __align__(16) float g_keysf[ROWS_ * LHD_];
__device__ __align__(16) float g_valsf[ROWS_ * LHD_];
__device__ __align__(16) float g_att[ROWS_ * HD_];
__device__ __align__(16) float g_h1[4 * ROWS_ * M_];
__device__ __align__(16) float g_h2[4 * ROWS_ * M_];
__device__ __align__(16) float g_h3[8 * ROWS_ * HD_];
__device__ __align__(16) float g_logits[8 * ROWS_ * R_];

// ---------------- threefry2x32 (exact JAX) ----------------
__host__ __device__ __forceinline__ uint32_t rotl32(uint32_t x, int r) {
    return (x << r) | (x >> (32 - r));
}
__host__ __device__ __forceinline__ void threefry2x32(
    uint32_t k0, uint32_t k1, uint32_t c0, uint32_t c1, uint32_t& o0, uint32_t& o1)
{
    uint32_t ks0 = k0, ks1 = k1, ks2 = k0 ^ k1 ^ 0x1BD11BDAu;
    uint32_t x0 = c0 + ks0, x1 = c1 + ks1;
#define TFR(r) { x0 += x1; x1 = rotl32(x1, r); x1 ^= x0; }
    TFR(13) TFR(15) TFR(26) TFR(6)
    x0 += ks1; x1 += ks2 + 1u;
    TFR(17) TFR(29) TFR(16) TFR(24)
    x0 += ks2; x1 += ks0 + 2u;
    TFR(13) TFR(15) TFR(26) TFR(6)
    x0 += ks0; x1 += ks1 + 3u;
    TFR(17) TFR(29) TFR(16) TFR(24)
    x0 += ks1; x1 += ks2 + 4u;
    TFR(13) TFR(15) TFR(26) TFR(6)
    x0 += ks2; x1 += ks0 + 5u;
#undef TFR
    o0 = x0; o1 = x1;
}
__device__ __forceinline__ uint32_t jax_random_bits32(uint32_t k0, uint32_t k1, uint32_t i) {
    uint32_t o0, o1;
    threefry2x32(k0, k1, 0u, i, o0, o1);
    return o0 ^ o1;
}
__device__ __forceinline__ float bits_to_unit_float(uint32_t bits) {
    return __uint_as_float((bits >> 9) | 0x3f800000u) - 1.0f;
}

// ---------------- tf32 / mma helpers ----------------
__device__ __forceinline__ uint32_t tf32_bits(float a) {
    uint32_t u;
    asm("cvt.rna.tf32.f32 %0, %1;" : "=r"(u) : "f"(a));
    return u;
}
__device__ __forceinline__ void mma8(float4& c, const uint4 a, const uint2 b) {
    asm volatile(
        "mma.sync.aligned.m16n8k8.row.col.f32.tf32.tf32.f32 "
        "{%0,%1,%2,%3}, {%4,%5,%6,%7}, {%8,%9}, {%0,%1,%2,%3};"
        : "+f"(c.x), "+f"(c.y), "+f"(c.z), "+f"(c.w)
        : "r"(a.x), "r"(a.y), "r"(a.z), "r"(a.w), "r"(b.x), "r"(b.y));
}
#define LDMX4(r, a) \
    asm volatile("ldmatrix.sync.aligned.m8n8.x4.shared.b16 {%0,%1,%2,%3}, [%4];" \
        : "=r"((r).x), "=r"((r).y), "=r"((r).z), "=r"((r).w) : "r"(a))

__device__ __forceinline__ uint32_t smem_u32(const void* p) {
    uint32_t a;
    asm("{ .reg .u64 t; cvta.to.shared.u64 t, %1; cvt.u32.u64 %0, t; }" : "=r"(a) : "l"(p));
    return a;
}

// smem stage layout (bytes): Ahi 8K | Alo 8K | Braw 17408  → 33792/stage, 2 stages
#define OFF_ALO 8192
#define OFF_BR  16384
#define STAGE_B 33792
#define SM_MMA  (2 * STAGE_B)   // 67584 (2 blocks/SM fit: 135KB < 227KB)

// A-load: plain, or relu(sum of NP partials)
template<int NP>
__device__ __forceinline__ float4 loadAf(const float* __restrict__ A, int offs, int psz) {
    float4 a = *(const float4*)&A[offs];
#pragma unroll
    for (int p = 1; p < NP; p++) {
        float4 b = *(const float4*)&A[offs + p * psz];
        a.x += b.x; a.y += b.y; a.z += b.z; a.w += b.w;
    }
    if (NP > 1) {
        a.x = fmaxf(a.x, 0.0f); a.y = fmaxf(a.y, 0.0f);
        a.z = fmaxf(a.z, 0.0f); a.w = fmaxf(a.w, 0.0f);
    }
    return a;
}

__device__ __forceinline__ void split4(float4 v, uint4& hi, uint4& lo) {
    hi.x = tf32_bits(v.x); lo.x = tf32_bits(v.x - __uint_as_float(hi.x));
    hi.y = tf32_bits(v.y); lo.y = tf32_bits(v.y - __uint_as_float(hi.y));
    hi.z = tf32_bits(v.z); lo.z = tf32_bits(v.z - __uint_as_float(hi.z));
    hi.w = tf32_bits(v.w); lo.w = tf32_bits(v.w - __uint_as_float(hi.w));
}

// ---------------- warp-MMA 3xTF32 GEMM body: 64x128 tile, BK=32, 2-stage ----------------
// 8 warps: warpM(0..1) x warpN(0..3), each 32m x 32n.
// A pre-split (hi/lo, SW128 swizzle, ldmatrix); B raw fp32, split at load.
// B element (n,k) at Wb[(n>>6)*blkStride + (n&63) + k*kStride].
template<int NP>
__device__ void mma_body(
    const float* __restrict__ A, int psz, int lda,
    const float* __restrict__ Wb, int blkStride, int kStride,
    const float* __restrict__ bias, int useBias,
    float* __restrict__ C, int ldc,
    int row0, int n0, int kStart, int kLen)
{
    extern __shared__ char smc[];
    const uint32_t smb = smem_u32(smc);
    const int tid = threadIdx.x;
    const int lane = tid & 31, wid = tid >> 5;
    const int warpM = wid >> 2, warpN = wid & 3;   // 2 x 4 warps -> 32m x 32n each

    float4 acc[2][4];
#pragma unroll
    for (int i = 0; i < 2; i++)
#pragma unroll
        for (int j = 0; j < 4; j++) acc[i][j] = make_float4(0.f, 0.f, 0.f, 0.f);

    float4 av[2], bv[4];

    auto load_g = [&](int k0) {
#pragma unroll
        for (int j = 0; j < 2; j++) {        // A: 512 slots (row 0..63, kc 0..7)
            int idx = tid + j * 256;
            int row = idx >> 3, kc = idx & 7;
            av[j] = loadAf<NP>(A, (row0 + row) * lda + k0 + kc * 4, psz);
        }
#pragma unroll
        for (int j = 0; j < 4; j++) {        // B: 1024 slots (n4, k)
            int idx = tid + j * 256;
            int n4 = (idx & 31) << 2, k = idx >> 5;
            int ng = n0 + n4;
            const float* bp = Wb + (size_t)(ng >> 6) * blkStride + (ng & 63)
                                 + (size_t)(k0 + k) * kStride;
            bv[j] = *(const float4*)bp;
        }
    };
    auto store_s = [&](int s) {
        char* st = smc + s * STAGE_B;
        float* Ah = (float*)st;
        float* Al = (float*)(st + OFF_ALO);
        float* Br = (float*)(st + OFF_BR);
#pragma unroll
        for (int j = 0; j < 2; j++) {        // A row-major + SW128 swizzle, pre-split
            int idx = tid + j * 256;
            int row = idx >> 3, kc = idx & 7;
            uint4 hi, lo; split4(av[j], hi, lo);
            int off = row * 32 + ((kc ^ (row & 7)) << 2);
            *(uint4*)&Ah[off] = hi;
            *(uint4*)&Al[off] = lo;
        }
#pragma unroll
        for (int j = 0; j < 4; j++) {        // B [k][n] raw, 136-float rows
            int idx = tid + j * 256;
            int n4 = (idx & 31) << 2, k = idx >> 5;
            *(float4*)&Br[k * 136 + n4] = bv[j];
        }
    };

    const int nIter = kLen >> 5;
    load_g(kStart);
    store_s(0);
    __syncthreads();
    int buf = 0;
    for (int it = 0; it < nIter; ++it) {
        if (it + 1 < nIter) load_g(kStart + ((it + 1) << 5));
        {
            const uint32_t stA = smb + buf * STAGE_B;
            const float* Br = (const float*)(smc + buf * STAGE_B + OFF_BR);
            const int i = lane & 7, g = lane >> 3;
            const int rbase = warpM * 32 + i + ((g & 1) << 3);
#pragma unroll
            for (int kblk = 0; kblk < 4; kblk++) {
                const int ch = ((kblk << 1) + (g >> 1)) ^ i;   // swizzled chunk
                uint4 ah[2], al[2];
#pragma unroll
                for (int mt = 0; mt < 2; mt++) {
                    uint32_t ad = stA + (uint32_t)(((rbase + mt * 16) * 32 + (ch << 2)) * 4);
                    LDMX4(ah[mt], ad);
                    LDMX4(al[mt], ad + OFF_ALO);
                }
#pragma unroll
                for (int nt = 0; nt < 4; nt++) {
                    const int kk = (kblk << 3) + (lane & 3);
                    const int nn = warpN * 32 + (nt << 3) + (lane >> 2);
                    float b0 = Br[kk * 136 + nn];
                    float b1 = Br[(kk + 4) * 136 + nn];
                    uint2 bh, bl;
                    bh.x = tf32_bits(b0); bl.x = tf32_bits(b0 - __uint_as_float(bh.x));
                    bh.y = tf32_bits(b1); bl.y = tf32_bits(b1 - __uint_as_float(bh.y));
#pragma unroll
                    for (int mt = 0; mt < 2; mt++) {
                        mma8(acc[mt][nt], ah[mt], bh);
                        mma8(acc[mt][nt], ah[mt], bl);
                        mma8(acc[mt][nt], al[mt], bh);
                    }
                }
            }
        }
        if (it + 1 < nIter) {
            store_s(buf ^ 1);
            __syncthreads();
            buf ^= 1;
        }
    }

    // epilogue
#pragma unroll
    for (int mt = 0; mt < 2; mt++) {
        int r = row0 + warpM * 32 + mt * 16 + (lane >> 2);
#pragma unroll
        for (int nt = 0; nt < 4; nt++) {
            int cc = n0 + warpN * 32 + nt * 8 + ((lane & 3) << 1);
            float2 v0 = make_float2(acc[mt][nt].x, acc[mt][nt].y);
            float2 v1 = make_float2(acc[mt][nt].z, acc[mt][nt].w);
            if (useBias) {
                float b0 = bias[cc], b1 = bias[cc + 1];
                v0.x += b0; v0.y += b1; v1.x += b0; v1.y += b1;
            }
            *(float2*)&C[(size_t)r * ldc + cc]       = v0;
            *(float2*)&C[(size_t)(r + 8) * ldc + cc] = v1;
        }
    }
}

// ---------------- wrappers ----------------
template<int NP>
__global__ __launch_bounds__(256, 2) void tc_gemm(
    const float* __restrict__ A, int psz, const float* __restrict__ W,
    const float* __restrict__ bias, float* __restrict__ C, int K, int N)
{
    int n0 = blockIdx.x << 7, row0 = blockIdx.y << 6, z = blockIdx.z;
    int kLen = K / gridDim.z;
    mma_body<NP>(A, psz, K, W, 64, N, bias, (z == 0) ? 1 : 0,
                 C + (size_t)z * ROWS_ * N, N, row0, n0, z * kLen, kLen);
}

__global__ __launch_bounds__(256, 2) void tc_qkv(
    const float* __restrict__ flow,
    const float* __restrict__ Wk, const float* __restrict__ bk,
    const float* __restrict__ Wv, const float* __restrict__ bv,
    const float* __restrict__ Wsh, const float* __restrict__ bsh,
    float* __restrict__ keys, float* __restrict__ vals, float* __restrict__ att)
{
    int bid = blockIdx.x;
    if (bid < 256) {                      // keys / vals; W layout [L*H][E][64]
        int isV = bid >> 7, j = bid & 127;
        int rt = j >> 4, nt = j & 15;     // 8 row tiles (64) x 16 col tiles (128)
        mma_body<1>(flow, 0, E_, isV ? Wv : Wk, E_ * 64, 64, isV ? bv : bk, 1,
                    isV ? vals : keys, LHD_, rt << 6, nt << 7, 0, E_);
    } else {                              // att0; W_shift [E][HD] row-major
        int j = bid - 256, rt = j >> 2, nt = j & 3;   // 8 x 4
        mma_body<1>(flow, 0, E_, Wsh, 64, HD_, bsh, 1, att, HD_,
                    rt << 6, nt << 7, 0, E_);
    }
}

// ---------------- block sum over 256 threads ----------------
__device__ __forceinline__ float block_sum256(float v, float* red) {
#pragma unroll
    for (int o = 16; o; o >>= 1) v += __shfl_xor_sync(0xffffffffu, v, o);
    int w = threadIdx.x >> 5;
    if ((threadIdx.x & 31) == 0) red[w] = v;
    __syncthreads();
    float tot = 0.0f;
#pragma unroll
    for (int k = 0; k < 8; k++) tot += red[k];
    __syncthreads();
    return tot;
}

// ---------------- attention + LN1, optional fused residual+LN2 of prior layer ----------------
template<int NPART>
__global__ __launch_bounds__(256) void attn_ln_kernel(
    const float* __restrict__ keysf, const float* __restrict__ valsf,
    float* __restrict__ att,
    const float* __restrict__ g1, const float* __restrict__ b1v, int l,
    const float* __restrict__ part,
    const float* __restrict__ g2, const float* __restrict__ b2v)
{
    int row = blockIdx.x;
    int bId = row >> 6;
    int t = threadIdx.x;
    __shared__ float qs[HD_];
    __shared__ float sp[HD_];
    __shared__ float red[8];

    int i0 = row * HD_ + t, i1 = i0 + 256;
    if (NPART > 0) {
        const int S = ROWS_ * HD_;
        float x0 = att[i0], x1 = att[i1];
#pragma unroll
        for (int q = 0; q < NPART; q++) { x0 += part[i0 + q * S]; x1 += part[i1 + q * S]; }
        float m = block_sum256(x0 + x1, red) * (1.0f / 512.0f);
        float d0 = x0 - m, d1 = x1 - m;
        float vv = block_sum256(d0 * d0 + d1 * d1, red) * (1.0f / 512.0f);
        float sc = 1.0f / sqrtf(vv + 1e-5f);
        int p = (l - 1) * HD_;
        qs[t]       = d0 * sc * g2[p + t]       + b2v[p + t];
        qs[t + 256] = d1 * sc * g2[p + t + 256] + b2v[p + t + 256];
    } else {
        qs[t]       = att[i0];
        qs[t + 256] = att[i1];
    }
    __syncthreads();

    int h = t >> 5, lane = t & 31;
    float s[2];
#pragma unroll
    for (int ww = 0; ww < 2; ww++) {
        int w = lane + ww * 32;
        const float* kp = &keysf[(bId * V_ + w) * LHD_ + (l * H_ + h) * D_];
        float accv = 0.0f;
#pragma unroll
        for (int d = 0; d < 64; d++) accv = fmaf(qs[h * 64 + d], kp[d], accv);
        s[ww] = accv * 0.125f;
    }
    float mx = fmaxf(s[0], s[1]);
#pragma unroll
    for (int o = 16; o; o >>= 1) mx = fmaxf(mx, __shfl_xor_sync(0xffffffffu, mx, o));
    float e0 = expf(s[0] - mx), e1 = expf(s[1] - mx);
    float sum = e0 + e1;
#pragma unroll
    for (int o = 16; o; o >>= 1) sum += __shfl_xor_sync(0xffffffffu, sum, o);
    sp[h * 64 + lane]      = e0 / sum;
    sp[h * 64 + lane + 32] = e1 / sum;
    __syncthreads();

    float r[2];
#pragma unroll
    for (int rep = 0; rep < 2; rep++) {
        int hd = t + rep * 256;
        int hh = hd >> 6, d = hd & 63;
        const float* vp = &valsf[(bId * V_) * LHD_ + (l * H_ + hh) * D_ + d];
        float accv = 0.0f;
#pragma unroll
        for (int w = 0; w < 64; w++) accv = fmaf(sp[hh * 64 + w], vp[w * LHD_], accv);
        r[rep] = qs[hd] + accv;
    }
    __syncthreads();

    float m = block_sum256(r[0] + r[1], red) * (1.0f / 512.0f);
    float d0 = r[0] - m, d1 = r[1] - m;
    float v = block_sum256(d0 * d0 + d1 * d1, red) * (1.0f / 512.0f);
    float scale = 1.0f / sqrtf(v + 1e-5f);
    att[i0] = d0 * scale * g1[l * HD_ + t]       + b1v[l * HD_ + t];
    att[i1] = d1 * scale * g1[l * HD_ + t + 256] + b1v[l * HD_ + t + 256];
}

// ---------------- final residual (8 partials) + LN2 ----------------
__global__ __launch_bounds__(256) void add_ln_kernel(
    const float* __restrict__ p, float* __restrict__ att,
    const float* __restrict__ g, const float* __restrict__ b, int l)
{
    int row = blockIdx.x;
    int t = threadIdx.x;
    __shared__ float red[8];
    const int S = ROWS_ * HD_;
    int i0 = row * HD_ + t, i1 = i0 + 256;
    float x0 = att[i0], x1 = att[i1];
#pragma unroll
    for (int q = 0; q < 8; q++) { x0 += p[i0 + q * S]; x1 += p[i1 + q * S]; }
    float m = block_sum256(x0 + x1, red) * (1.0f / 512.0f);
    float d0 = x0 - m, d1 = x1 - m;
    float v = block_sum256(d0 * d0 + d1 * d1, red) * (1.0f / 512.0f);
    float scale = 1.0f / sqrtf(v + 1e-5f);
    att[i0] = d0 * scale * g[l * HD_ + t]       + b[l * HD_ + t];
    att[i1] = d1 * scale * g[l * HD_ + t + 256] + b[l * HD_ + t + 256];
}

// ---------------- fused gumbel + argmax + uniform + output ----------------
__global__ __launch_bounds__(256) void sample_kernel(
    const float* __restrict__ logits, float* __restrict__ out,
    uint32_t kc0, uint32_t kc1, uint32_t ku0, uint32_t ku1)
{
    int warp = threadIdx.x >> 5, lane = threadIdx.x & 31;
    int j = blockIdx.x * 8 + warp;
    int bv = j >> 5;
    const int SL = ROWS_ * R_;
    const float tiny = 1.17549435e-38f;
    float best = -__int_as_float(0x7f800000);
    int bidx = 0;
#pragma unroll
    for (int q = 0; q < 4; q++) {
        int r = lane + q * 32;
        float lgv = 0.0f;
#pragma unroll
        for (int z = 0; z < 8; z++) lgv += logits[z * SL + bv * R_ + r];
        uint32_t bits = jax_random_bits32(kc0, kc1, (uint32_t)(j * R_ + r));
        float u = fmaxf(bits_to_unit_float(bits), tiny);
        float gmb = -logf(-logf(u));
        float v = gmb + lgv;
        if (v > best) { best = v; bidx = r; }
    }
#pragma unroll
    for (int o = 16; o; o >>= 1) {
        float ov = __shfl_xor_sync(0xffffffffu, best, o);
        int   oi = __shfl_xor_sync(0xffffffffu, bidx, o);
        if (ov > best || (ov == best && oi < bidx)) { best = ov; bidx = oi; }
    }
    if (lane == 0) {
        uint32_t bits = jax_random_bits32(ku0, ku1, (uint32_t)j);
        float u = bits_to_unit_float(bits);
        out[j] = ((float)bidx + u) * (1.0f / 128.0f);
    }
}

// ---------------- launch ----------------
extern "C" void kernel_launch(void* const* d_in, const int* in_sizes, int n_in,
                              void* d_out, int out_size)
{
    int iflow = 0, iWshift = 1, ibshift = 2, iWk = 3, ibk = 4, iWv = 5, ibv = 6,
        iln1g = 7, iln1b = 8, iW1 = 9, ib1 = 10, iW2 = 11, ib2 = 12, iW3 = 13,
        ib3 = 14, iln2g = 15, iln2b = 16, iWdist = 17, ibdist = 18;
    if (in_sizes[0] == 2097152) {   // alphabetical fallback
        iW1 = 0; iW2 = 1; iW3 = 2; iWdist = 3; iWshift = 4; iWk = 5; iWv = 6;
        ib1 = 7; ib2 = 8; ib3 = 9; ibdist = 10; ibshift = 11; ibk = 12; ibv = 13;
        iflow = 14; iln1b = 15; iln1g = 16; iln2b = 17; iln2g = 18;
    }

    const float* flow    = (const float*)d_in[iflow];
    const float* W_shift = (const float*)d_in[iWshift];
    const float* b_shift = (const float*)d_in[ibshift];
    const float* Wk      = (const float*)d_in[iWk];
    const float* bk      = (const float*)d_in[ibk];
    const float* Wv      = (const float*)d_in[iWv];
    const float* bv      = (const float*)d_in[ibv];
    const float* ln1_g   = (const float*)d_in[iln1g];
    const float* ln1_b   = (const float*)d_in[iln1b];
    const float* W1      = (const float*)d_in[iW1];
    const float* b1      = (const float*)d_in[ib1];
    const float* W2      = (const float*)d_in[iW2];
    const float* b2      = (const float*)d_in[ib2];
    const float* W3      = (const float*)d_in[iW3];
    const float* b3      = (const float*)d_in[ib3];
    const float* ln2_g   = (const float*)d_in[iln2g];
    const float* ln2_b   = (const float*)d_in[iln2b];
    const float* W_dist  = (const float*)d_in[iWdist];
    const float* b_dist  = (const float*)d_in[ibdist];

    float *keysf, *valsf, *att, *h1, *h2, *h3, *logits;
    cudaGetSymbolAddress((void**)&keysf,  g_keysf);
    cudaGetSymbolAddress((void**)&valsf,  g_valsf);
    cudaGetSymbolAddress((void**)&att,    g_att);
    cudaGetSymbolAddress((void**)&h1,     g_h1);
    cudaGetSymbolAddress((void**)&h2,     g_h2);
    cudaGetSymbolAddress((void**)&h3,     g_h3);
    cudaGetSymbolAddress((void**)&logits, g_logits);

    cudaFuncSetAttribute(tc_qkv,     cudaFuncAttributeMaxDynamicSharedMemorySize, SM_MMA);
    cudaFuncSetAttribute(tc_gemm<1>, cudaFuncAttributeMaxDynamicSharedMemorySize, SM_MMA);
    cudaFuncSetAttribute(tc_gemm<4>, cudaFuncAttributeMaxDynamicSharedMemorySize, SM_MMA);

    uint32_t kc0, kc1, ku0, ku1;
    threefry2x32(0u, 1u, 0u, 0u, kc0, kc1);
    threefry2x32(0u, 1u, 0u, 1u, ku0, ku1);

    const int PH = ROWS_ * M_;

    // keys + vals + att0 (288 x 64x128 tiles, tensor path)
    tc_qkv<<<288, 256, SM_MMA>>>(flow, Wk, bk, Wv, bv, W_shift, b_shift,
                                 keysf, valsf, att);

    attn_ln_kernel<0><<<ROWS_, 256>>>(keysf, valsf, att, ln1_g, ln1_b, 0,
                                      nullptr, nullptr, nullptr);

    for (int l = 0; l < L_; l++) {
        tc_gemm<1><<<dim3(8, 8, 4), 256, SM_MMA>>>(att, 0,
            W1 + (size_t)l * HD_ * M_, b1 + l * M_, h1, HD_, M_);
        tc_gemm<4><<<dim3(8, 8, 4), 256, SM_MMA>>>(h1, PH,
            W2 + (size_t)l * M_ * M_, b2 + l * M_, h2, M_, M_);
        tc_gemm<4><<<dim3(4, 8, 8), 256, SM_MMA>>>(h2, PH,
            W3 + (size_t)l * M_ * HD_, b3 + l * HD_, h3, M_, HD_);
        if (l < L_ - 1) {
            attn_ln_kernel<8><<<ROWS_, 256>>>(keysf, valsf, att,
                                              ln1_g, ln1_b, l + 1,
                                              h3, ln2_g, ln2_b);
        } else {
            add_ln_kernel<<<ROWS_, 256>>>(h3, att, ln2_g, ln2_b, l);
        }
    }

    tc_gemm<1><<<dim3(1, 8, 8), 256, SM_MMA>>>(att, 0, W_dist, b_dist,
                                               logits, HD_, R_);

    sample_kernel<<<2048, 256>>>(logits, (float*)d_out, kc0, kc1, ku0, ku1);
}

// round 17
// speedup vs baseline: 1.5843x; 1.5843x over previous
#include <cuda_runtime.h>
#include <cstdint>

#define B_ 8
#define V_ 64
#define E_ 512
#define L_ 4
#define H_ 8
#define D_ 64
#define M_ 1024
#define R_ 128
#define HD_ 512
#define ROWS_ 512
#define LHD_ 2048

// ---------------- scratch ----------------
__device__ __align__(16) float g_keysf[ROWS_ * LHD_];
__device__ __align__(16) float g_valsf[ROWS_ * LHD_];
__device__ __align__(16) float g_att[ROWS_ * HD_];
__device__ __align__(16) float g_h1[4 * ROWS_ * M_];
__device__ __align__(16) float g_h2[4 * ROWS_ * M_];
__device__ __align__(16) float g_h3[8 * ROWS_ * HD_];
__device__ __align__(16) float g_logits[8 * ROWS_ * R_];

// ---------------- threefry2x32 (exact JAX) ----------------
__host__ __device__ __forceinline__ uint32_t rotl32(uint32_t x, int r) {
    return (x << r) | (x >> (32 - r));
}
__host__ __device__ __forceinline__ void threefry2x32(
    uint32_t k0, uint32_t k1, uint32_t c0, uint32_t c1, uint32_t& o0, uint32_t& o1)
{
    uint32_t ks0 = k0, ks1 = k1, ks2 = k0 ^ k1 ^ 0x1BD11BDAu;
    uint32_t x0 = c0 + ks0, x1 = c1 + ks1;
#define TFR(r) { x0 += x1; x1 = rotl32(x1, r); x1 ^= x0; }
    TFR(13) TFR(15) TFR(26) TFR(6)
    x0 += ks1; x1 += ks2 + 1u;
    TFR(17) TFR(29) TFR(16) TFR(24)
    x0 += ks2; x1 += ks0 + 2u;
    TFR(13) TFR(15) TFR(26) TFR(6)
    x0 += ks0; x1 += ks1 + 3u;
    TFR(17) TFR(29) TFR(16) TFR(24)
    x0 += ks1; x1 += ks2 + 4u;
    TFR(13) TFR(15) TFR(26) TFR(6)
    x0 += ks2; x1 += ks0 + 5u;
#undef TFR
    o0 = x0; o1 = x1;
}
__device__ __forceinline__ uint32_t jax_random_bits32(uint32_t k0, uint32_t k1, uint32_t i) {
    uint32_t o0, o1;
    threefry2x32(k0, k1, 0u, i, o0, o1);
    return o0 ^ o1;
}
__device__ __forceinline__ float bits_to_unit_float(uint32_t bits) {
    return __uint_as_float((bits >> 9) | 0x3f800000u) - 1.0f;
}

// ---------------- tf32 / mma helpers ----------------
__device__ __forceinline__ uint32_t tf32_bits(float a) {
    uint32_t u;
    asm("cvt.rna.tf32.f32 %0, %1;" : "=r"(u) : "f"(a));
    return u;
}
__device__ __forceinline__ void mma8(float4& c, const uint4 a, const uint2 b) {
    asm volatile(
        "mma.sync.aligned.m16n8k8.row.col.f32.tf32.tf32.f32 "
        "{%0,%1,%2,%3}, {%4,%5,%6,%7}, {%8,%9}, {%0,%1,%2,%3};"
        : "+f"(c.x), "+f"(c.y), "+f"(c.z), "+f"(c.w)
        : "r"(a.x), "r"(a.y), "r"(a.z), "r"(a.w), "r"(b.x), "r"(b.y));
}
#define LDMX4(r, a) \
    asm volatile("ldmatrix.sync.aligned.m8n8.x4.shared.b16 {%0,%1,%2,%3}, [%4];" \
        : "=r"((r).x), "=r"((r).y), "=r"((r).z), "=r"((r).w) : "r"(a))

__device__ __forceinline__ uint32_t smem_u32(const void* p) {
    uint32_t a;
    asm("{ .reg .u64 t; cvta.to.shared.u64 t, %1; cvt.u32.u64 %0, t; }" : "=r"(a) : "l"(p));
    return a;
}
#define CP_ASYNC16(dst, src) \
    asm volatile("cp.async.cg.shared.global [%0], [%1], 16;" :: "r"(dst), "l"(src) : "memory")
#define CP_COMMIT()  asm volatile("cp.async.commit_group;" ::: "memory")
#define CP_WAIT0()   asm volatile("cp.async.wait_group 0;" ::: "memory")

// smem stage layout (bytes): Ahi 16K | Alo 16K | Braw 17408  → 50176/stage
#define OFF_ALO 16384
#define OFF_BR  32768
#define STAGE_B 50176
#define SM_MMA  (2 * STAGE_B)   // 100352

// A-load: plain, or relu(sum of NP partials)
template<int NP>
__device__ __forceinline__ float4 loadAf(const float* __restrict__ A, int offs, int psz) {
    float4 a = *(const float4*)&A[offs];
#pragma unroll
    for (int p = 1; p < NP; p++) {
        float4 b = *(const float4*)&A[offs + p * psz];
        a.x += b.x; a.y += b.y; a.z += b.z; a.w += b.w;
    }
    if (NP > 1) {
        a.x = fmaxf(a.x, 0.0f); a.y = fmaxf(a.y, 0.0f);
        a.z = fmaxf(a.z, 0.0f); a.w = fmaxf(a.w, 0.0f);
    }
    return a;
}

__device__ __forceinline__ void split4(float4 v, uint4& hi, uint4& lo) {
    hi.x = tf32_bits(v.x); lo.x = tf32_bits(v.x - __uint_as_float(hi.x));
    hi.y = tf32_bits(v.y); lo.y = tf32_bits(v.y - __uint_as_float(hi.y));
    hi.z = tf32_bits(v.z); lo.z = tf32_bits(v.z - __uint_as_float(hi.z));
    hi.w = tf32_bits(v.w); lo.w = tf32_bits(v.w - __uint_as_float(hi.w));
}

// ---------------- warp-MMA 3xTF32 GEMM body: 128x128, BK=32, 2-stage ----------------
// 8 warps: warpM(0..1) x warpN(0..3), each 64m x 32n.
// A pre-split (hi/lo, SW128 swizzle, ldmatrix); B raw fp32 via cp.async, split at load.
// B element (n,k) at Wb[(n>>6)*blkStride + (n&63) + k*kStride].
template<int NP>
__device__ void mma_body(
    const float* __restrict__ A, int psz, int lda,
    const float* __restrict__ Wb, int blkStride, int kStride,
    const float* __restrict__ bias, int useBias,
    float* __restrict__ C, int ldc,
    int row0, int n0, int kStart, int kLen)
{
    extern __shared__ char smc[];
    const uint32_t smb = smem_u32(smc);
    const int tid = threadIdx.x;
    const int lane = tid & 31, wid = tid >> 5;
    const int warpM = wid >> 2, warpN = wid & 3;   // 2 x 4 warps -> 64m x 32n

    float4 acc[4][4];
#pragma unroll
    for (int i = 0; i < 4; i++)
#pragma unroll
        for (int j = 0; j < 4; j++) acc[i][j] = make_float4(0.f, 0.f, 0.f, 0.f);

    float4 av[4];

    // B fill via cp.async into stage s (raw fp32, [k][n] rows of 136 floats)
    auto cpasync_B = [&](int s, int k0) {
        uint32_t dstB = smb + s * STAGE_B + OFF_BR;
#pragma unroll
        for (int j = 0; j < 4; j++) {
            int idx = tid + j * 256;
            int n4 = (idx & 31) << 2, k = idx >> 5;
            int ng = n0 + n4;
            const float* src = Wb + (size_t)(ng >> 6) * blkStride + (ng & 63)
                                  + (size_t)(k0 + k) * kStride;
            CP_ASYNC16(dstB + (uint32_t)((k * 136 + n4) << 2), src);
        }
        CP_COMMIT();
    };
    auto loadA_g = [&](int k0) {
#pragma unroll
        for (int j = 0; j < 4; j++) {
            int idx = tid + j * 256;
            int row = idx >> 3, kc = idx & 7;
            av[j] = loadAf<NP>(A, (row0 + row) * lda + k0 + kc * 4, psz);
        }
    };
    auto storeA_s = [&](int s) {
        char* st = smc + s * STAGE_B;
        float* Ah = (float*)st;
        float* Al = (float*)(st + OFF_ALO);
#pragma unroll
        for (int j = 0; j < 4; j++) {
            int idx = tid + j * 256;
            int row = idx >> 3, kc = idx & 7;
            uint4 hi, lo; split4(av[j], hi, lo);
            int off = row * 32 + ((kc ^ (row & 7)) << 2);
            *(uint4*)&Ah[off] = hi;
            *(uint4*)&Al[off] = lo;
        }
    };

    const int nIter = kLen >> 5;
    cpasync_B(0, kStart);
    loadA_g(kStart);
    storeA_s(0);
    CP_WAIT0();
    __syncthreads();
    int buf = 0;
    for (int it = 0; it < nIter; ++it) {
        if (it + 1 < nIter) {
            cpasync_B(buf ^ 1, kStart + ((it + 1) << 5));   // overlaps with compute below
            loadA_g(kStart + ((it + 1) << 5));
        }
        {
            const uint32_t stA = smb + buf * STAGE_B;
            const float* Br = (const float*)(smc + buf * STAGE_B + OFF_BR);
            const int i = lane & 7, g = lane >> 3;
            const int rbase = warpM * 64 + i + ((g & 1) << 3);
#pragma unroll
            for (int kblk = 0; kblk < 4; kblk++) {
                const int ch = ((kblk << 1) + (g >> 1)) ^ i;   // swizzled chunk
                uint4 ah[4], al[4];
#pragma unroll
                for (int mt = 0; mt < 4; mt++) {
                    uint32_t ad = stA + (uint32_t)(((rbase + mt * 16) * 32 + (ch << 2)) * 4);
                    LDMX4(ah[mt], ad);
                    LDMX4(al[mt], ad + OFF_ALO);
                }
#pragma unroll
                for (int nt = 0; nt < 4; nt++) {
                    const int kk = (kblk << 3) + (lane & 3);
                    const int nn = warpN * 32 + (nt << 3) + (lane >> 2);
                    float b0 = Br[kk * 136 + nn];
                    float b1 = Br[(kk + 4) * 136 + nn];
                    uint2 bh, bl;
                    bh.x = tf32_bits(b0); bl.x = tf32_bits(b0 - __uint_as_float(bh.x));
                    bh.y = tf32_bits(b1); bl.y = tf32_bits(b1 - __uint_as_float(bh.y));
#pragma unroll
                    for (int mt = 0; mt < 4; mt++) {
                        mma8(acc[mt][nt], ah[mt], bh);
                        mma8(acc[mt][nt], ah[mt], bl);
                        mma8(acc[mt][nt], al[mt], bh);
                    }
                }
            }
        }
        if (it + 1 < nIter) {
            storeA_s(buf ^ 1);
            CP_WAIT0();
            __syncthreads();
            buf ^= 1;
        }
    }

    // epilogue
#pragma unroll
    for (int mt = 0; mt < 4; mt++) {
        int r = row0 + warpM * 64 + mt * 16 + (lane >> 2);
#pragma unroll
        for (int nt = 0; nt < 4; nt++) {
            int cc = n0 + warpN * 32 + nt * 8 + ((lane & 3) << 1);
            float2 v0 = make_float2(acc[mt][nt].x, acc[mt][nt].y);
            float2 v1 = make_float2(acc[mt][nt].z, acc[mt][nt].w);
            if (useBias) {
                float b0 = bias[cc], b1 = bias[cc + 1];
                v0.x += b0; v0.y += b1; v1.x += b0; v1.y += b1;
            }
            *(float2*)&C[(size_t)r * ldc + cc]       = v0;
            *(float2*)&C[(size_t)(r + 8) * ldc + cc] = v1;
        }
    }
}

// ---------------- wrappers ----------------
template<int NP>
__global__ __launch_bounds__(256) void tc_gemm(
    const float* __restrict__ A, int psz, const float* __restrict__ W,
    const float* __restrict__ bias, float* __restrict__ C, int K, int N)
{
    int n0 = blockIdx.x << 7, row0 = blockIdx.y << 7, z = blockIdx.z;
    int kLen = K / gridDim.z;
    mma_body<NP>(A, psz, K, W, 64, N, bias, (z == 0) ? 1 : 0,
                 C + (size_t)z * ROWS_ * N, N, row0, n0, z * kLen, kLen);
}

__global__ __launch_bounds__(256) void tc_qkv(
    const float* __restrict__ flow,
    const float* __restrict__ Wk, const float* __restrict__ bk,
    const float* __restrict__ Wv, const float* __restrict__ bv,
    const float* __restrict__ Wsh, const float* __restrict__ bsh,
    float* __restrict__ keys, float* __restrict__ vals, float* __restrict__ att)
{
    int bid = blockIdx.x;
    if (bid < 128) {                      // keys / vals; W layout [L*H][E][64]
        int isV = bid >> 6, j = bid & 63;
        int rt = j >> 4, nt = j & 15;
        mma_body<1>(flow, 0, E_, isV ? Wv : Wk, E_ * 64, 64, isV ? bv : bk, 1,
                    isV ? vals : keys, LHD_, rt << 7, nt << 7, 0, E_);
    } else {                              // att0; W_shift [E][HD] row-major
        int j = bid - 128, rt = j >> 2, nt = j & 3;
        mma_body<1>(flow, 0, E_, Wsh, 64, HD_, bsh, 1, att, HD_,
                    rt << 7, nt << 7, 0, E_);
    }
}

// ---------------- block sum over 256 threads ----------------
__device__ __forceinline__ float block_sum256(float v, float* red) {
#pragma unroll
    for (int o = 16; o; o >>= 1) v += __shfl_xor_sync(0xffffffffu, v, o);
    int w = threadIdx.x >> 5;
    if ((threadIdx.x & 31) == 0) red[w] = v;
    __syncthreads();
    float tot = 0.0f;
#pragma unroll
    for (int k = 0; k < 8; k++) tot += red[k];
    __syncthreads();
    return tot;
}

// ---------------- attention + LN1, optional fused residual+LN2 of prior layer ----------------
template<int NPART>
__global__ __launch_bounds__(256) void attn_ln_kernel(
    const float* __restrict__ keysf, const float* __restrict__ valsf,
    float* __restrict__ att,
    const float* __restrict__ g1, const float* __restrict__ b1v, int l,
    const float* __restrict__ part,
    const float* __restrict__ g2, const float* __restrict__ b2v)
{
    int row = blockIdx.x;
    int bId = row >> 6;
    int t = threadIdx.x;
    __shared__ float qs[HD_];
    __shared__ float sp[HD_];
    __shared__ float red[8];

    int i0 = row * HD_ + t, i1 = i0 + 256;
    if (NPART > 0) {
        const int S = ROWS_ * HD_;
        float x0 = att[i0], x1 = att[i1];
#pragma unroll
        for (int q = 0; q < NPART; q++) { x0 += part[i0 + q * S]; x1 += part[i1 + q * S]; }
        float m = block_sum256(x0 + x1, red) * (1.0f / 512.0f);
        float d0 = x0 - m, d1 = x1 - m;
        float vv = block_sum256(d0 * d0 + d1 * d1, red) * (1.0f / 512.0f);
        float sc = 1.0f / sqrtf(vv + 1e-5f);
        int p = (l - 1) * HD_;
        qs[t]       = d0 * sc * g2[p + t]       + b2v[p + t];
        qs[t + 256] = d1 * sc * g2[p + t + 256] + b2v[p + t + 256];
    } else {
        qs[t]       = att[i0];
        qs[t + 256] = att[i1];
    }
    __syncthreads();

    int h = t >> 5, lane = t & 31;
    float s[2];
#pragma unroll
    for (int ww = 0; ww < 2; ww++) {
        int w = lane + ww * 32;
        const float* kp = &keysf[(bId * V_ + w) * LHD_ + (l * H_ + h) * D_];
        float accv = 0.0f;
#pragma unroll
        for (int d = 0; d < 64; d++) accv = fmaf(qs[h * 64 + d], kp[d], accv);
        s[ww] = accv * 0.125f;
    }
    float mx = fmaxf(s[0], s[1]);
#pragma unroll
    for (int o = 16; o; o >>= 1) mx = fmaxf(mx, __shfl_xor_sync(0xffffffffu, mx, o));
    float e0 = expf(s[0] - mx), e1 = expf(s[1] - mx);
    float sum = e0 + e1;
#pragma unroll
    for (int o = 16; o; o >>= 1) sum += __shfl_xor_sync(0xffffffffu, sum, o);
    sp[h * 64 + lane]      = e0 / sum;
    sp[h * 64 + lane + 32] = e1 / sum;
    __syncthreads();

    float r[2];
#pragma unroll
    for (int rep = 0; rep < 2; rep++) {
        int hd = t + rep * 256;
        int hh = hd >> 6, d = hd & 63;
        const float* vp = &valsf[(bId * V_) * LHD_ + (l * H_ + hh) * D_ + d];
        float accv = 0.0f;
#pragma unroll
        for (int w = 0; w < 64; w++) accv = fmaf(sp[hh * 64 + w], vp[w * LHD_], accv);
        r[rep] = qs[hd] + accv;
    }
    __syncthreads();

    float m = block_sum256(r[0] + r[1], red) * (1.0f / 512.0f);
    float d0 = r[0] - m, d1 = r[1] - m;
    float v = block_sum256(d0 * d0 + d1 * d1, red) * (1.0f / 512.0f);
    float scale = 1.0f / sqrtf(v + 1e-5f);
    att[i0] = d0 * scale * g1[l * HD_ + t]       + b1v[l * HD_ + t];
    att[i1] = d1 * scale * g1[l * HD_ + t + 256] + b1v[l * HD_ + t + 256];
}

// ---------------- final residual (8 partials) + LN2 ----------------
__global__ __launch_bounds__(256) void add_ln_kernel(
    const float* __restrict__ p, float* __restrict__ att,
    const float* __restrict__ g, const float* __restrict__ b, int l)
{
    int row = blockIdx.x;
    int t = threadIdx.x;
    __shared__ float red[8];
    const int S = ROWS_ * HD_;
    int i0 = row * HD_ + t, i1 = i0 + 256;
    float x0 = att[i0], x1 = att[i1];
#pragma unroll
    for (int q = 0; q < 8; q++) { x0 += p[i0 + q * S]; x1 += p[i1 + q * S]; }
    float m = block_sum256(x0 + x1, red) * (1.0f / 512.0f);
    float d0 = x0 - m, d1 = x1 - m;
    float v = block_sum256(d0 * d0 + d1 * d1, red) * (1.0f / 512.0f);
    float scale = 1.0f / sqrtf(v + 1e-5f);
    att[i0] = d0 * scale * g[l * HD_ + t]       + b[l * HD_ + t];
    att[i1] = d1 * scale * g[l * HD_ + t + 256] + b[l * HD_ + t + 256];
}

// ---------------- fused gumbel + argmax + uniform + output ----------------
__global__ __launch_bounds__(256) void sample_kernel(
    const float* __restrict__ logits, float* __restrict__ out,
    uint32_t kc0, uint32_t kc1, uint32_t ku0, uint32_t ku1)
{
    int warp = threadIdx.x >> 5, lane = threadIdx.x & 31;
    int j = blockIdx.x * 8 + warp;
    int bv = j >> 5;
    const int SL = ROWS_ * R_;
    const float tiny = 1.17549435e-38f;
    float best = -__int_as_float(0x7f800000);
    int bidx = 0;
#pragma unroll
    for (int q = 0; q < 4; q++) {
        int r = lane + q * 32;
        float lgv = 0.0f;
#pragma unroll
        for (int z = 0; z < 8; z++) lgv += logits[z * SL + bv * R_ + r];
        uint32_t bits = jax_random_bits32(kc0, kc1, (uint32_t)(j * R_ + r));
        float u = fmaxf(bits_to_unit_float(bits), tiny);
        float gmb = -logf(-logf(u));
        float v = gmb + lgv;
        if (v > best) { best = v; bidx = r; }
    }
#pragma unroll
    for (int o = 16; o; o >>= 1) {
        float ov = __shfl_xor_sync(0xffffffffu, best, o);
        int   oi = __shfl_xor_sync(0xffffffffu, bidx, o);
        if (ov > best || (ov == best && oi < bidx)) { best = ov; bidx = oi; }
    }
    if (lane == 0) {
        uint32_t bits = jax_random_bits32(ku0, ku1, (uint32_t)j);
        float u = bits_to_unit_float(bits);
        out[j] = ((float)bidx + u) * (1.0f / 128.0f);
    }
}

// ---------------- launch ----------------
extern "C" void kernel_launch(void* const* d_in, const int* in_sizes, int n_in,
                              void* d_out, int out_size)
{
    int iflow = 0, iWshift = 1, ibshift = 2, iWk = 3, ibk = 4, iWv = 5, ibv = 6,
        iln1g = 7, iln1b = 8, iW1 = 9, ib1 = 10, iW2 = 11, ib2 = 12, iW3 = 13,
        ib3 = 14, iln2g = 15, iln2b = 16, iWdist = 17, ibdist = 18;
    if (in_sizes[0] == 2097152) {   // alphabetical fallback
        iW1 = 0; iW2 = 1; iW3 = 2; iWdist = 3; iWshift = 4; iWk = 5; iWv = 6;
        ib1 = 7; ib2 = 8; ib3 = 9; ibdist = 10; ibshift = 11; ibk = 12; ibv = 13;
        iflow = 14; iln1b = 15; iln1g = 16; iln2b = 17; iln2g = 18;
    }

    const float* flow    = (const float*)d_in[iflow];
    const float* W_shift = (const float*)d_in[iWshift];
    const float* b_shift = (const float*)d_in[ibshift];
    const float* Wk      = (const float*)d_in[iWk];
    const float* bk      = (const float*)d_in[ibk];
    const float* Wv      = (const float*)d_in[iWv];
    const float* bv      = (const float*)d_in[ibv];
    const float* ln1_g   = (const float*)d_in[iln1g];
    const float* ln1_b   = (const float*)d_in[iln1b];
    const float* W1      = (const float*)d_in[iW1];
    const float* b1      = (const float*)d_in[ib1];
    const float* W2      = (const float*)d_in[iW2];
    const float* b2      = (const float*)d_in[ib2];
    const float* W3      = (const float*)d_in[iW3];
    const float* b3      = (const float*)d_in[ib3];
    const float* ln2_g   = (const float*)d_in[iln2g];
    const float* ln2_b   = (const float*)d_in[iln2b];
    const float* W_dist  = (const float*)d_in[iWdist];
    const float* b_dist  = (const float*)d_in[ibdist];

    float *keysf, *valsf, *att, *h1, *h2, *h3, *logits;
    cudaGetSymbolAddress((void**)&keysf,  g_keysf);
    cudaGetSymbolAddress((void**)&valsf,  g_valsf);
    cudaGetSymbolAddress((void**)&att,    g_att);
    cudaGetSymbolAddress((void**)&h1,     g_h1);
    cudaGetSymbolAddress((void**)&h2,     g_h2);
    cudaGetSymbolAddress((void**)&h3,     g_h3);
    cudaGetSymbolAddress((void**)&logits, g_logits);

    cudaFuncSetAttribute(tc_qkv,     cudaFuncAttributeMaxDynamicSharedMemorySize, SM_MMA);
    cudaFuncSetAttribute(tc_gemm<1>, cudaFuncAttributeMaxDynamicSharedMemorySize, SM_MMA);
    cudaFuncSetAttribute(tc_gemm<4>, cudaFuncAttributeMaxDynamicSharedMemorySize, SM_MMA);

    uint32_t kc0, kc1, ku0, ku1;
    threefry2x32(0u, 1u, 0u, 0u, kc0, kc1);
    threefry2x32(0u, 1u, 0u, 1u, ku0, ku1);

    const int PH = ROWS_ * M_;

    // keys + vals + att0 (144 x 128x128 tiles, tensor path)
    tc_qkv<<<144, 256, SM_MMA>>>(flow, Wk, bk, Wv, bv, W_shift, b_shift,
                                 keysf, valsf, att);

    attn_ln_kernel<0><<<ROWS_, 256>>>(keysf, valsf, att, ln1_g, ln1_b, 0,
                                      nullptr, nullptr, nullptr);

    for (int l = 0; l < L_; l++) {
        tc_gemm<1><<<dim3(8, 4, 4), 256, SM_MMA>>>(att, 0,
            W1 + (size_t)l * HD_ * M_, b1 + l * M_, h1, HD_, M_);
        tc_gemm<4><<<dim3(8, 4, 4), 256, SM_MMA>>>(h1, PH,
            W2 + (size_t)l * M_ * M_, b2 + l * M_, h2, M_, M_);
        tc_gemm<4><<<dim3(4, 4, 8), 256, SM_MMA>>>(h2, PH,
            W3 + (size_t)l * M_ * HD_, b3 + l * HD_, h3, M_, HD_);
        if (l < L_ - 1) {
            attn_ln_kernel<8><<<ROWS_, 256>>>(keysf, valsf, att,
                                              ln1_g, ln1_b, l + 1,
                                              h3, ln2_g, ln2_b);
        } else {
            add_ln_kernel<<<ROWS_, 256>>>(h3, att, ln2_g, ln2_b, l);
        }
    }

    tc_gemm<1><<<dim3(1, 4, 8), 256, SM_MMA>>>(att, 0, W_dist, b_dist,
                                               logits, HD_, R_);

    sample_kernel<<<2048, 256>>>(logits, (float*)d_out, kc0, kc1, ku0, ku1);
}